// round 13
// baseline (speedup 1.0000x reference)
#include <cuda_runtime.h>
#include <math.h>

#define BIGV   100000000.0f
#define GAMMA_ 0.05f
#define INVG_  20.0f
#define WARPP  256.0f
#define K_     4
#define B_     8
#define KB_    32
#define N_     800
#define C_     80
#define S_     128
#define Z_     32

// diagonal-major D: g_Dd[kb][d-2][n] = D[n][m], d-2 = n+m (0-indexed)
#define DDROWS_ 1608

// ---- scratch (device globals; no runtime allocation) ----
__device__ float g_sx[(size_t)KB_ * N_ * C_];   // sigmoid(mel_iters)
__device__ float g_sy[(size_t)B_  * N_ * C_];   // sigmoid(mel_targets)
__device__ float g_x2[KB_ * N_];                // row norms of sx
__device__ float g_y2[B_  * N_];                // row norms of sy
__device__ float g_Dd[(size_t)KB_ * DDROWS_ * N_];  // diagonal-major distances
__device__ float g_d [KB_];                     // DTW costs

// ============================================================
// Kernel 1: sigmoid + squared row norms. One warp per row.
// ============================================================
__global__ void prep_kernel(const float* __restrict__ mel_iters,
                            const float* __restrict__ mel_targets) {
    int wid  = (blockIdx.x * blockDim.x + threadIdx.x) >> 5;
    int lane = threadIdx.x & 31;
    const int xrows = KB_ * N_;
    const int total = xrows + B_ * N_;
    if (wid >= total) return;

    const float* src;
    float* dst;
    float* nrm;
    if (wid < xrows) {
        src = mel_iters + (size_t)wid * C_;
        dst = g_sx      + (size_t)wid * C_;
        nrm = g_x2 + wid;
    } else {
        int r = wid - xrows;
        src = mel_targets + (size_t)r * C_;
        dst = g_sy        + (size_t)r * C_;
        nrm = g_y2 + r;
    }
    float acc = 0.f;
    for (int c = lane; c < C_; c += 32) {
        float v = src[c];
        float s = 1.f / (1.f + expf(-v));
        dst[c] = s;
        acc += s * s;
    }
    #pragma unroll
    for (int o = 16; o; o >>= 1) acc += __shfl_xor_sync(0xffffffffu, acc, o);
    if (lane == 0) *nrm = acc;
}

// ============================================================
// Kernel 2: distance GEMM with diagonal-major epilogue.
// (identical to the 612us version)
// ============================================================
__global__ void __launch_bounds__(256) dist_gemm_kernel() {
    __shared__ float sA[80 * 65];
    __shared__ float sB[80 * 65];

    const int kb = blockIdx.z;
    const int b  = kb & 7;
    const int m0 = blockIdx.x * 64;
    const int n0 = blockIdx.y * 64;
    const int t  = threadIdx.x;

    const float* xbase = g_sx + (size_t)kb * N_ * C_ + (size_t)n0 * C_;
    const float* ybase = g_sy + (size_t)b  * N_ * C_ + (size_t)m0 * C_;

    for (int e = t; e < 64 * 80; e += 256) {
        int r = e / 80;
        int c = e - r * 80;
        float xv = (n0 + r < N_) ? xbase[r * C_ + c] : 0.f;
        float yv = (m0 + r < N_) ? ybase[r * C_ + c] : 0.f;
        sA[c * 65 + r] = xv;
        sB[c * 65 + r] = yv;
    }
    __syncthreads();

    const int tx = t & 15;
    const int ty = t >> 4;

    float acc[4][4];
    #pragma unroll
    for (int i = 0; i < 4; i++)
        #pragma unroll
        for (int j = 0; j < 4; j++) acc[i][j] = 0.f;

    #pragma unroll 8
    for (int k = 0; k < 80; k++) {
        float a[4], bb[4];
        #pragma unroll
        for (int i = 0; i < 4; i++) a[i]  = sA[k * 65 + ty * 4 + i];
        #pragma unroll
        for (int j = 0; j < 4; j++) bb[j] = sB[k * 65 + tx * 4 + j];
        #pragma unroll
        for (int i = 0; i < 4; i++)
            #pragma unroll
            for (int j = 0; j < 4; j++)
                acc[i][j] = fmaf(a[i], bb[j], acc[i][j]);
    }

    // ---- epilogue: D values -> smem tile (stride 66) ----
    __syncthreads();
    float* sD = sA;

    {
        int nb = ty * 4, mb = tx * 4;
        float xn[4], ym[4];
        #pragma unroll
        for (int ii = 0; ii < 4; ii++) {
            int n = n0 + nb + ii;
            int m = m0 + mb + ii;
            xn[ii] = g_x2[kb * N_ + (n < N_ ? n : N_ - 1)];
            ym[ii] = g_y2[b  * N_ + (m < N_ ? m : N_ - 1)];
        }
        #pragma unroll
        for (int ii = 0; ii < 4; ii++)
            #pragma unroll
            for (int jj = 0; jj < 4; jj++)
                sD[(nb + ii) * 66 + (mb + jj)] = xn[ii] + ym[jj] - 2.f * acc[ii][jj];
    }
    __syncthreads();

    // ---- write 127 local anti-diagonals, coalesced in n ----
    {
        const int w8   = t >> 5;
        const int lane = t & 31;
        float* DdBase = g_Dd + (size_t)kb * ((size_t)DDROWS_ * N_);
        for (int ld = w8; ld < 127; ld += 8) {
            int nlo = ld > 63 ? ld - 63 : 0;
            int nhi = ld < 63 ? ld : 63;
            for (int nl = nlo + lane; nl <= nhi; nl += 32) {
                int ml = ld - nl;
                int n = n0 + nl, m = m0 + ml;
                if (n < N_ && m < N_)
                    DdBase[(size_t)(n + m) * N_ + n] = sD[nl * 66 + ml];
            }
        }
    }
}

// ============================================================
// Kernel 3: soft-DTW — epoch-skewed warp pipeline, shfl-minimal.
// (identical to the 612us version; launched TWICE this round as
// a deliberate timing decomposition — idempotent on g_d)
// ============================================================
#define NWARP_  25
#define EW_     32
#define NWIN_   26
#define RINGSZ_ 128
#define RMASK_  (RINGSZ_ - 1)

__device__ __forceinline__ float softmin3(float a, float bu, float c) {
    float m = fminf(a, fminf(bu, c));
    float d1 = a - m, d2 = bu - m, d3 = c - m;
    float second = d1 + d2 + d3 - fmaxf(d1, fmaxf(d2, d3));
    float sm = m;
    if (second < 1.0f) {
        sm = m - GAMMA_ * __logf(__expf(-d1 * INVG_) +
                                 __expf(-d2 * INVG_) +
                                 __expf(-d3 * INVG_));
    }
    return sm;
}

__global__ void __launch_bounds__(NWARP_ * 32) dtw_kernel() {
    __shared__ float bnd[NWARP_][RINGSZ_];

    const int kb   = blockIdx.x;
    const int w    = threadIdx.x >> 5;
    const int lane = threadIdx.x & 31;
    const int i    = 32 * w + lane + 1;
    const int dstart = 32 * w + 2;

    __syncthreads();

    const float* DdCol = g_Dd + (size_t)kb * ((size_t)DDROWS_ * N_) + 32 * w + lane;
    const unsigned FULL = 0xffffffffu;

    float one_r    = BIGV;   // R[i][.] at diag d-1
    float up_two_c = BIGV;   // cached shfl_up(two_r) == prev step's up_one

    const int NEPOCH = 2 * (NWARP_ - 1) + NWIN_;   // 74
    for (int e = 0; e < NEPOCH; e++) {
        int k = e - 2 * w;
        if (k >= 0 && k < NWIN_) {
            const int A = dstart + EW_ * k;

            float pre_a = BIGV, pre_b = BIGV;
            if (w > 0) {
                pre_a = bnd[w - 1][(A - 2 + lane) & RMASK_];
                pre_b = bnd[w - 1][(A + lane) & RMASK_];
            }

            if (k == 0) {
                float t0 = __shfl_sync(FULL, pre_a, 0);
                if (lane == 0) up_two_c = (w == 0) ? 0.f : t0;
            }

            #define STEP(s_, Dval_) {                                           \
                const int d = A + (s_);                                         \
                float b_one_v;                                                  \
                if ((s_) < 31) b_one_v = __shfl_sync(FULL, pre_a, (s_) + 1);    \
                else           b_one_v = __shfl_sync(FULL, pre_b, 30);          \
                if (w == 0) b_one_v = BIGV;                                     \
                float up_one = __shfl_up_sync(FULL, one_r, 1);                  \
                if (lane == 0) up_one = b_one_v;                                \
                int j = d - i;                                                  \
                float rv = BIGV;                                                \
                if (j >= 1 && j <= N_)                                          \
                    rv = (Dval_) + softmin3(up_two_c, up_one + WARPP,           \
                                            one_r + WARPP);                     \
                up_two_c = up_one;                                              \
                one_r = rv;                                                     \
                if (lane == 31) {                                               \
                    bnd[w][d & RMASK_] = rv;                                    \
                    if (w == NWARP_ - 1 && d == 2 * N_) g_d[kb] = rv;           \
                }                                                               \
            }

            float bufA[8], bufB[8], bufC[8];
            #pragma unroll
            for (int q = 0; q < 8; q++) bufA[q] = __ldg(DdCol + (size_t)(A - 2 + q) * N_);
            #pragma unroll
            for (int q = 0; q < 8; q++) bufB[q] = __ldg(DdCol + (size_t)(A + 6 + q) * N_);

            #pragma unroll
            for (int q = 0; q < 8; q++) bufC[q] = __ldg(DdCol + (size_t)(A + 14 + q) * N_);
            #pragma unroll
            for (int q = 0; q < 8; q++) STEP(q, bufA[q]);

            #pragma unroll
            for (int q = 0; q < 8; q++) bufA[q] = __ldg(DdCol + (size_t)(A + 22 + q) * N_);
            #pragma unroll
            for (int q = 0; q < 8; q++) STEP(8 + q, bufB[q]);

            #pragma unroll
            for (int q = 0; q < 8; q++) STEP(16 + q, bufC[q]);

            #pragma unroll
            for (int q = 0; q < 8; q++) STEP(24 + q, bufA[q]);

            #undef STEP
        }
        __syncthreads();
    }
}

// ============================================================
// Kernel 4: finalize scalar losses (parallel, ~6.5us).
// ============================================================
__global__ void finalize_kernel(const int* __restrict__ mel_lens,
                                const int* __restrict__ src_lens,
                                const float* __restrict__ durations,
                                const float* __restrict__ mus,
                                const float* __restrict__ log_vars,
                                const int* __restrict__ step_p,
                                float* __restrict__ out) {
    __shared__ float s_kl[8];
    __shared__ float s_dur[B_];
    __shared__ float s_d[KB_];

    int t    = threadIdx.x;      // 256 threads
    int lane = t & 31;
    int w    = t >> 5;

    {
        float lv = log_vars[t];
        float mu = mus[t];
        float kl = 1.f + lv - mu * mu - expf(lv);
        #pragma unroll
        for (int o = 16; o; o >>= 1) kl += __shfl_xor_sync(0xffffffffu, kl, o);
        if (lane == 0) s_kl[w] = kl;
    }

    {
        float ds = durations[w * S_ + lane] + durations[w * S_ + 32 + lane]
                 + durations[w * S_ + 64 + lane] + durations[w * S_ + 96 + lane];
        #pragma unroll
        for (int o = 16; o; o >>= 1) ds += __shfl_xor_sync(0xffffffffu, ds, o);
        if (lane == 0) s_dur[w] = ds;
    }

    if (t < KB_) s_d[t] = g_d[t];
    __syncthreads();

    if (t == 0) {
        float klsum = 0.f;
        #pragma unroll
        for (int i = 0; i < 8; i++) klsum += s_kl[i];
        float kl_loss = -0.5f * klsum;

        float sum_d = 0.f;
        #pragma unroll
        for (int p = 0; p < KB_; p++) sum_d += s_d[p];
        float mel_iter_loss = sum_d / (float)B_;

        float mel = 0.f, durl = 0.f;
        #pragma unroll
        for (int b = 0; b < B_; b++) {
            float len = (float)mel_lens[b];
            mel += mel_iter_loss / ((float)K_ * len);
            durl += fabsf(s_dur[b] - len) / (float)src_lens[b];
        }
        mel  /= (float)B_;
        durl  = 2.f * durl / (float)B_;

        int step = step_p[0];
        float beta;
        if (step < 2000)       beta = 0.f;
        else if (step >= 8000) beta = 1.f;
        else                   beta = (float)(step - 2000) / 6000.f;

        float total = mel + durl + beta * kl_loss;
        out[0] = total;
        out[1] = mel;
        out[2] = durl;
        out[3] = kl_loss;
        out[4] = beta;
    }
}

// ============================================================
extern "C" void kernel_launch(void* const* d_in, const int* in_sizes, int n_in,
                              void* d_out, int out_size) {
    const float* mel_iters   = (const float*)d_in[0];
    const float* mel_targets = (const float*)d_in[1];
    const int*   mel_lens    = (const int*)  d_in[2];
    const int*   src_lens    = (const int*)  d_in[3];
    const float* durations   = (const float*)d_in[4];
    const float* mus         = (const float*)d_in[5];
    const float* log_vars    = (const float*)d_in[6];
    const int*   step        = (const int*)  d_in[7];
    float*       out         = (float*)d_out;

    (void)in_sizes; (void)n_in; (void)out_size;

    const int total_rows = KB_ * N_ + B_ * N_;
    const int wpb = 8;
    prep_kernel<<<(total_rows + wpb - 1) / wpb, wpb * 32>>>(mel_iters, mel_targets);

    dim3 g((N_ + 63) / 64, (N_ + 63) / 64, KB_);
    dist_gemm_kernel<<<g, 256>>>();

    // DTW launched twice ON PURPOSE this round: idempotent on g_d, so
    // correctness is unchanged and delta(dur_us) vs R12 = exact DTW cost.
    dtw_kernel<<<KB_, NWARP_ * 32>>>();
    dtw_kernel<<<KB_, NWARP_ * 32>>>();

    finalize_kernel<<<1, 256>>>(mel_lens, src_lens, durations, mus, log_vars, step, out);
}

// round 14
// speedup vs baseline: 1.3307x; 1.3307x over previous
#include <cuda_runtime.h>
#include <math.h>

#define BIGV   100000000.0f
#define GAMMA_ 0.05f
#define INVG_  20.0f
#define WARPP  256.0f
#define K_     4
#define B_     8
#define KB_    32
#define N_     800
#define C_     80
#define S_     128
#define Z_     32

// diagonal-major D: g_Dd[kb][d-2][n] = D[n][m], d-2 = n+m (0-indexed)
// rows padded so RPT=2 prefetch (rows up to 1631) never reads past the end
#define DDROWS_ 1640

// ---- scratch (device globals; no runtime allocation) ----
__device__ float g_sx[(size_t)KB_ * N_ * C_];   // sigmoid(mel_iters)
__device__ float g_sy[(size_t)B_  * N_ * C_];   // sigmoid(mel_targets)
__device__ float g_x2[KB_ * N_];                // row norms of sx
__device__ float g_y2[B_  * N_];                // row norms of sy
__device__ float g_Dd[(size_t)KB_ * DDROWS_ * N_];  // diagonal-major distances
__device__ float g_d [KB_];                     // DTW costs

// ============================================================
// Kernel 1: sigmoid + squared row norms. One warp per row.
// ============================================================
__global__ void prep_kernel(const float* __restrict__ mel_iters,
                            const float* __restrict__ mel_targets) {
    int wid  = (blockIdx.x * blockDim.x + threadIdx.x) >> 5;
    int lane = threadIdx.x & 31;
    const int xrows = KB_ * N_;
    const int total = xrows + B_ * N_;
    if (wid >= total) return;

    const float* src;
    float* dst;
    float* nrm;
    if (wid < xrows) {
        src = mel_iters + (size_t)wid * C_;
        dst = g_sx      + (size_t)wid * C_;
        nrm = g_x2 + wid;
    } else {
        int r = wid - xrows;
        src = mel_targets + (size_t)r * C_;
        dst = g_sy        + (size_t)r * C_;
        nrm = g_y2 + r;
    }
    float acc = 0.f;
    for (int c = lane; c < C_; c += 32) {
        float v = src[c];
        float s = 1.f / (1.f + expf(-v));
        dst[c] = s;
        acc += s * s;
    }
    #pragma unroll
    for (int o = 16; o; o >>= 1) acc += __shfl_xor_sync(0xffffffffu, acc, o);
    if (lane == 0) *nrm = acc;
}

// ============================================================
// Kernel 2: distance GEMM with diagonal-major epilogue.
// (identical to the 612us version)
// ============================================================
__global__ void __launch_bounds__(256) dist_gemm_kernel() {
    __shared__ float sA[80 * 65];
    __shared__ float sB[80 * 65];

    const int kb = blockIdx.z;
    const int b  = kb & 7;
    const int m0 = blockIdx.x * 64;
    const int n0 = blockIdx.y * 64;
    const int t  = threadIdx.x;

    const float* xbase = g_sx + (size_t)kb * N_ * C_ + (size_t)n0 * C_;
    const float* ybase = g_sy + (size_t)b  * N_ * C_ + (size_t)m0 * C_;

    for (int e = t; e < 64 * 80; e += 256) {
        int r = e / 80;
        int c = e - r * 80;
        float xv = (n0 + r < N_) ? xbase[r * C_ + c] : 0.f;
        float yv = (m0 + r < N_) ? ybase[r * C_ + c] : 0.f;
        sA[c * 65 + r] = xv;
        sB[c * 65 + r] = yv;
    }
    __syncthreads();

    const int tx = t & 15;
    const int ty = t >> 4;

    float acc[4][4];
    #pragma unroll
    for (int i = 0; i < 4; i++)
        #pragma unroll
        for (int j = 0; j < 4; j++) acc[i][j] = 0.f;

    #pragma unroll 8
    for (int k = 0; k < 80; k++) {
        float a[4], bb[4];
        #pragma unroll
        for (int i = 0; i < 4; i++) a[i]  = sA[k * 65 + ty * 4 + i];
        #pragma unroll
        for (int j = 0; j < 4; j++) bb[j] = sB[k * 65 + tx * 4 + j];
        #pragma unroll
        for (int i = 0; i < 4; i++)
            #pragma unroll
            for (int j = 0; j < 4; j++)
                acc[i][j] = fmaf(a[i], bb[j], acc[i][j]);
    }

    // ---- epilogue: D values -> smem tile (stride 66) ----
    __syncthreads();
    float* sD = sA;

    {
        int nb = ty * 4, mb = tx * 4;
        float xn[4], ym[4];
        #pragma unroll
        for (int ii = 0; ii < 4; ii++) {
            int n = n0 + nb + ii;
            int m = m0 + mb + ii;
            xn[ii] = g_x2[kb * N_ + (n < N_ ? n : N_ - 1)];
            ym[ii] = g_y2[b  * N_ + (m < N_ ? m : N_ - 1)];
        }
        #pragma unroll
        for (int ii = 0; ii < 4; ii++)
            #pragma unroll
            for (int jj = 0; jj < 4; jj++)
                sD[(nb + ii) * 66 + (mb + jj)] = xn[ii] + ym[jj] - 2.f * acc[ii][jj];
    }
    __syncthreads();

    // ---- write 127 local anti-diagonals, coalesced in n ----
    {
        const int w8   = t >> 5;
        const int lane = t & 31;
        float* DdBase = g_Dd + (size_t)kb * ((size_t)DDROWS_ * N_);
        for (int ld = w8; ld < 127; ld += 8) {
            int nlo = ld > 63 ? ld - 63 : 0;
            int nhi = ld < 63 ? ld : 63;
            for (int nl = nlo + lane; nl <= nhi; nl += 32) {
                int ml = ld - nl;
                int n = n0 + nl, m = m0 + ml;
                if (n < N_ && m < N_)
                    DdBase[(size_t)(n + m) * N_ + n] = sD[nl * 66 + ml];
            }
        }
    }
}

// ============================================================
// Kernel 3: soft-DTW — epoch-skewed warp pipeline, RPT=2.
// 13 warps; warp w owns rows 64w+1..64w+64; lane l owns rows
// i0=64w+2l+1, i1=i0+1 (both cells of a diagonal are mutually
// independent -> computed in parallel from d-1/d-2 state).
// One boundary broadcast + one shfl_up serve BOTH cells.
// D loads are coalesced float2. Slow softmin path is gated by a
// warp-uniform __any_sync vote so its MUFU chain issues only
// when some lane needs it (result provably unchanged: for
// second>=1 the fp32 logsumexp rounds to exactly m).
// Lag = 3 epochs/warp (verified: producer completes diag A+30
// by end of epoch e-1, margin 1; ring span <= 66 < 128).
// ============================================================
#define NW2_    13
#define LAG_    3
#define NWIN2_  27     // 27*32 = 864 >= N+63 = 863 diags per warp
#define RING2_  128
#define RM2_    (RING2_ - 1)

__global__ void __launch_bounds__(NW2_ * 32) dtw_kernel() {
    __shared__ float bnd[NW2_][RING2_];   // bnd[w][d & 127] = R[64w+64][d-(64w+64)]

    const int kb   = blockIdx.x;
    const int w    = threadIdx.x >> 5;
    const int lane = threadIdx.x & 31;
    const int i0   = 64 * w + 2 * lane + 1;
    const int i1   = i0 + 1;
    const bool v0  = (i0 <= N_);
    const bool v1  = (i1 <= N_);
    const int dstart = 64 * w + 2;

    __syncthreads();

    // float2 view of diag row: row r, pair (i0-1, i1-1) = float2 index 32w+lane
    const float2* Dd2 = (const float2*)g_Dd
                      + (size_t)kb * ((size_t)DDROWS_ * (N_ / 2))
                      + 32 * w + lane;
    const unsigned FULL = 0xffffffffu;

    float one0 = BIGV;      // R[i0][d-1]
    float one1 = BIGV;      // R[i1][d-1]
    float two0 = BIGV;      // R[i0][d-2]
    float up_two_c = BIGV;  // R[i0-1][d-2] (cached from prev step's up_one)

    const int NEPOCH = LAG_ * (NW2_ - 1) + NWIN2_;   // 63
    for (int e = 0; e < NEPOCH; e++) {
        int k = e - LAG_ * w;
        if (k >= 0 && k < NWIN2_) {
            const int A = dstart + 32 * k;

            // preload producer boundary (row 64w): diags A-2+lane, A+lane
            float pre_a = BIGV, pre_b = BIGV;
            if (w > 0) {
                pre_a = bnd[w - 1][(A - 2 + lane) & RM2_];
                pre_b = bnd[w - 1][(A + lane) & RM2_];
            }

            if (k == 0) {
                float t0 = __shfl_sync(FULL, pre_a, 0);
                if (lane == 0) up_two_c = (w == 0) ? 0.f : t0;  // R[0][0]=0 at d=2
            }

            // one DP step at diagonal d = A + s computing cells (i0, i1)
            #define STEP(s_, Dv_) {                                              \
                const int d = A + (s_);                                          \
                float b_one_v;                                                   \
                if ((s_) < 31) b_one_v = __shfl_sync(FULL, pre_a, (s_) + 1);     \
                else           b_one_v = __shfl_sync(FULL, pre_b, 30);           \
                if (w == 0) b_one_v = BIGV;                                      \
                float up_one = __shfl_up_sync(FULL, one1, 1);                    \
                if (lane == 0) up_one = b_one_v;                                 \
                float buW = up_one + WARPP;                                      \
                float c0W = one0 + WARPP;   /* left of cell0 == up of cell1 */   \
                float c1W = one1 + WARPP;                                        \
                int j0 = d - i0;                                                 \
                bool g0 = (j0 >= 1) && (j0 <= N_) && v0;                         \
                bool g1 = (j0 >= 2) && (j0 <= N_ + 1) && v1;  /* j1=j0-1 */      \
                float m0 = fminf(up_two_c, fminf(buW, c0W));                     \
                float d10 = up_two_c - m0, d20 = buW - m0, d30 = c0W - m0;       \
                float sec0 = d10 + d20 + d30 - fmaxf(d10, fmaxf(d20, d30));      \
                float m1 = fminf(two0, fminf(c0W, c1W));                         \
                float d11 = two0 - m1, d21 = c0W - m1, d31 = c1W - m1;           \
                float sec1 = d11 + d21 + d31 - fmaxf(d11, fmaxf(d21, d31));      \
                float sm0 = m0, sm1 = m1;                                        \
                if (__any_sync(FULL, (sec0 < 1.0f) || (sec1 < 1.0f))) {          \
                    if (sec0 < 1.0f)                                             \
                        sm0 = m0 - GAMMA_ * __logf(__expf(-d10 * INVG_) +        \
                                                   __expf(-d20 * INVG_) +        \
                                                   __expf(-d30 * INVG_));        \
                    if (sec1 < 1.0f)                                             \
                        sm1 = m1 - GAMMA_ * __logf(__expf(-d11 * INVG_) +        \
                                                   __expf(-d21 * INVG_) +        \
                                                   __expf(-d31 * INVG_));        \
                }                                                                \
                float rv0 = g0 ? ((Dv_).x + sm0) : BIGV;                         \
                float rv1 = g1 ? ((Dv_).y + sm1) : BIGV;                         \
                two0 = one0;                                                     \
                one0 = rv0;                                                      \
                one1 = rv1;                                                      \
                up_two_c = up_one;                                               \
                if (lane == 31) bnd[w][d & RM2_] = rv1;                          \
                if (d == 2 * N_ && i1 == N_) g_d[kb] = rv1;                      \
            }

            float2 bufA[8], bufB[8], bufC[8];
            // groups 0 (rows A-2..A+5) and 1 (rows A+6..A+13)
            #pragma unroll
            for (int q = 0; q < 8; q++) bufA[q] = Dd2[(size_t)(A - 2 + q) * (N_ / 2)];
            #pragma unroll
            for (int q = 0; q < 8; q++) bufB[q] = Dd2[(size_t)(A + 6 + q) * (N_ / 2)];

            // g=0: prefetch group 2, consume group 0
            #pragma unroll
            for (int q = 0; q < 8; q++) bufC[q] = Dd2[(size_t)(A + 14 + q) * (N_ / 2)];
            #pragma unroll
            for (int q = 0; q < 8; q++) STEP(q, bufA[q]);

            // g=1: prefetch group 3 (into bufA), consume group 1
            #pragma unroll
            for (int q = 0; q < 8; q++) bufA[q] = Dd2[(size_t)(A + 22 + q) * (N_ / 2)];
            #pragma unroll
            for (int q = 0; q < 8; q++) STEP(8 + q, bufB[q]);

            // g=2: consume group 2
            #pragma unroll
            for (int q = 0; q < 8; q++) STEP(16 + q, bufC[q]);

            // g=3: consume group 3
            #pragma unroll
            for (int q = 0; q < 8; q++) STEP(24 + q, bufA[q]);

            #undef STEP
        }
        __syncthreads();
    }
}

// ============================================================
// Kernel 4: finalize scalar losses (parallel, ~6.5us).
// ============================================================
__global__ void finalize_kernel(const int* __restrict__ mel_lens,
                                const int* __restrict__ src_lens,
                                const float* __restrict__ durations,
                                const float* __restrict__ mus,
                                const float* __restrict__ log_vars,
                                const int* __restrict__ step_p,
                                float* __restrict__ out) {
    __shared__ float s_kl[8];
    __shared__ float s_dur[B_];
    __shared__ float s_d[KB_];

    int t    = threadIdx.x;      // 256 threads
    int lane = t & 31;
    int w    = t >> 5;

    {
        float lv = log_vars[t];
        float mu = mus[t];
        float kl = 1.f + lv - mu * mu - expf(lv);
        #pragma unroll
        for (int o = 16; o; o >>= 1) kl += __shfl_xor_sync(0xffffffffu, kl, o);
        if (lane == 0) s_kl[w] = kl;
    }

    {
        float ds = durations[w * S_ + lane] + durations[w * S_ + 32 + lane]
                 + durations[w * S_ + 64 + lane] + durations[w * S_ + 96 + lane];
        #pragma unroll
        for (int o = 16; o; o >>= 1) ds += __shfl_xor_sync(0xffffffffu, ds, o);
        if (lane == 0) s_dur[w] = ds;
    }

    if (t < KB_) s_d[t] = g_d[t];
    __syncthreads();

    if (t == 0) {
        float klsum = 0.f;
        #pragma unroll
        for (int i = 0; i < 8; i++) klsum += s_kl[i];
        float kl_loss = -0.5f * klsum;

        float sum_d = 0.f;
        #pragma unroll
        for (int p = 0; p < KB_; p++) sum_d += s_d[p];
        float mel_iter_loss = sum_d / (float)B_;

        float mel = 0.f, durl = 0.f;
        #pragma unroll
        for (int b = 0; b < B_; b++) {
            float len = (float)mel_lens[b];
            mel += mel_iter_loss / ((float)K_ * len);
            durl += fabsf(s_dur[b] - len) / (float)src_lens[b];
        }
        mel  /= (float)B_;
        durl  = 2.f * durl / (float)B_;

        int step = step_p[0];
        float beta;
        if (step < 2000)       beta = 0.f;
        else if (step >= 8000) beta = 1.f;
        else                   beta = (float)(step - 2000) / 6000.f;

        float total = mel + durl + beta * kl_loss;
        out[0] = total;
        out[1] = mel;
        out[2] = durl;
        out[3] = kl_loss;
        out[4] = beta;
    }
}

// ============================================================
extern "C" void kernel_launch(void* const* d_in, const int* in_sizes, int n_in,
                              void* d_out, int out_size) {
    const float* mel_iters   = (const float*)d_in[0];
    const float* mel_targets = (const float*)d_in[1];
    const int*   mel_lens    = (const int*)  d_in[2];
    const int*   src_lens    = (const int*)  d_in[3];
    const float* durations   = (const float*)d_in[4];
    const float* mus         = (const float*)d_in[5];
    const float* log_vars    = (const float*)d_in[6];
    const int*   step        = (const int*)  d_in[7];
    float*       out         = (float*)d_out;

    (void)in_sizes; (void)n_in; (void)out_size;

    const int total_rows = KB_ * N_ + B_ * N_;
    const int wpb = 8;
    prep_kernel<<<(total_rows + wpb - 1) / wpb, wpb * 32>>>(mel_iters, mel_targets);

    dim3 g((N_ + 63) / 64, (N_ + 63) / 64, KB_);
    dist_gemm_kernel<<<g, 256>>>();

    dtw_kernel<<<KB_, NW2_ * 32>>>();

    finalize_kernel<<<1, 256>>>(mel_lens, src_lens, durations, mus, log_vars, step, out);
}

// round 15
// speedup vs baseline: 1.5930x; 1.1971x over previous
#include <cuda_runtime.h>
#include <cuda_fp16.h>
#include <math.h>

#define BIGV   100000000.0f
#define GAMMA_ 0.05f
#define INVG_  20.0f
#define WARPP  256.0f
#define K_     4
#define B_     8
#define KB_    32
#define N_     800
#define C_     80
#define S_     128
#define Z_     32

// diagonal-major D (fp16): g_Dd[kb][d-2][n] = D[n][m], d-2 = n+m
// fp16 halves the footprint: 32*1608*800*2 = 82 MB -> fits 126 MB L2
#define DDROWS_ 1608

// ---- scratch (device globals; no runtime allocation) ----
__device__ float  g_sx[(size_t)KB_ * N_ * C_];
__device__ float  g_sy[(size_t)B_  * N_ * C_];
__device__ float  g_x2[KB_ * N_];
__device__ float  g_y2[B_  * N_];
__device__ __half g_Dd[(size_t)KB_ * DDROWS_ * N_];
__device__ float  g_d [KB_];

// ============================================================
// Kernel 1: sigmoid + squared row norms. One warp per row.
// ============================================================
__global__ void prep_kernel(const float* __restrict__ mel_iters,
                            const float* __restrict__ mel_targets) {
    int wid  = (blockIdx.x * blockDim.x + threadIdx.x) >> 5;
    int lane = threadIdx.x & 31;
    const int xrows = KB_ * N_;
    const int total = xrows + B_ * N_;
    if (wid >= total) return;

    const float* src;
    float* dst;
    float* nrm;
    if (wid < xrows) {
        src = mel_iters + (size_t)wid * C_;
        dst = g_sx      + (size_t)wid * C_;
        nrm = g_x2 + wid;
    } else {
        int r = wid - xrows;
        src = mel_targets + (size_t)r * C_;
        dst = g_sy        + (size_t)r * C_;
        nrm = g_y2 + r;
    }
    float acc = 0.f;
    for (int c = lane; c < C_; c += 32) {
        float v = src[c];
        float s = 1.f / (1.f + expf(-v));
        dst[c] = s;
        acc += s * s;
    }
    #pragma unroll
    for (int o = 16; o; o >>= 1) acc += __shfl_xor_sync(0xffffffffu, acc, o);
    if (lane == 0) *nrm = acc;
}

// ============================================================
// Kernel 2: distance GEMM with diagonal-major fp16 epilogue.
// (mainloop identical to the 612us version; only the final
// global store converts to __half)
// ============================================================
__global__ void __launch_bounds__(256) dist_gemm_kernel() {
    __shared__ float sA[80 * 65];
    __shared__ float sB[80 * 65];

    const int kb = blockIdx.z;
    const int b  = kb & 7;
    const int m0 = blockIdx.x * 64;
    const int n0 = blockIdx.y * 64;
    const int t  = threadIdx.x;

    const float* xbase = g_sx + (size_t)kb * N_ * C_ + (size_t)n0 * C_;
    const float* ybase = g_sy + (size_t)b  * N_ * C_ + (size_t)m0 * C_;

    for (int e = t; e < 64 * 80; e += 256) {
        int r = e / 80;
        int c = e - r * 80;
        float xv = (n0 + r < N_) ? xbase[r * C_ + c] : 0.f;
        float yv = (m0 + r < N_) ? ybase[r * C_ + c] : 0.f;
        sA[c * 65 + r] = xv;
        sB[c * 65 + r] = yv;
    }
    __syncthreads();

    const int tx = t & 15;
    const int ty = t >> 4;

    float acc[4][4];
    #pragma unroll
    for (int i = 0; i < 4; i++)
        #pragma unroll
        for (int j = 0; j < 4; j++) acc[i][j] = 0.f;

    #pragma unroll 8
    for (int k = 0; k < 80; k++) {
        float a[4], bb[4];
        #pragma unroll
        for (int i = 0; i < 4; i++) a[i]  = sA[k * 65 + ty * 4 + i];
        #pragma unroll
        for (int j = 0; j < 4; j++) bb[j] = sB[k * 65 + tx * 4 + j];
        #pragma unroll
        for (int i = 0; i < 4; i++)
            #pragma unroll
            for (int j = 0; j < 4; j++)
                acc[i][j] = fmaf(a[i], bb[j], acc[i][j]);
    }

    // ---- epilogue: D values -> smem tile (stride 66) ----
    __syncthreads();
    float* sD = sA;

    {
        int nb = ty * 4, mb = tx * 4;
        float xn[4], ym[4];
        #pragma unroll
        for (int ii = 0; ii < 4; ii++) {
            int n = n0 + nb + ii;
            int m = m0 + mb + ii;
            xn[ii] = g_x2[kb * N_ + (n < N_ ? n : N_ - 1)];
            ym[ii] = g_y2[b  * N_ + (m < N_ ? m : N_ - 1)];
        }
        #pragma unroll
        for (int ii = 0; ii < 4; ii++)
            #pragma unroll
            for (int jj = 0; jj < 4; jj++)
                sD[(nb + ii) * 66 + (mb + jj)] = xn[ii] + ym[jj] - 2.f * acc[ii][jj];
    }
    __syncthreads();

    // ---- write 127 local anti-diagonals (fp16), coalesced in n ----
    {
        const int w8   = t >> 5;
        const int lane = t & 31;
        __half* DdBase = g_Dd + (size_t)kb * ((size_t)DDROWS_ * N_);
        for (int ld = w8; ld < 127; ld += 8) {
            int nlo = ld > 63 ? ld - 63 : 0;
            int nhi = ld < 63 ? ld : 63;
            for (int nl = nlo + lane; nl <= nhi; nl += 32) {
                int ml = ld - nl;
                int n = n0 + nl, m = m0 + ml;
                if (n < N_ && m < N_)
                    DdBase[(size_t)(n + m) * N_ + n] = __float2half_rn(sD[nl * 66 + ml]);
            }
        }
    }
}

// ============================================================
// Kernel 3: soft-DTW — epoch-skewed warp pipeline (R12 612us
// structure, byte-identical logic), with fp16 D loads (L2-
// resident now) converted to fp32 on consumption.
// ============================================================
#define NWARP_  25
#define EW_     32
#define NWIN_   26
#define RINGSZ_ 128
#define RMASK_  (RINGSZ_ - 1)

__device__ __forceinline__ float softmin3(float a, float bu, float c) {
    float m = fminf(a, fminf(bu, c));
    float d1 = a - m, d2 = bu - m, d3 = c - m;
    float second = d1 + d2 + d3 - fmaxf(d1, fmaxf(d2, d3));
    float sm = m;
    if (second < 1.0f) {
        sm = m - GAMMA_ * __logf(__expf(-d1 * INVG_) +
                                 __expf(-d2 * INVG_) +
                                 __expf(-d3 * INVG_));
    }
    return sm;
}

__global__ void __launch_bounds__(NWARP_ * 32) dtw_kernel() {
    __shared__ float bnd[NWARP_][RINGSZ_];

    const int kb   = blockIdx.x;
    const int w    = threadIdx.x >> 5;
    const int lane = threadIdx.x & 31;
    const int i    = 32 * w + lane + 1;
    const int dstart = 32 * w + 2;

    __syncthreads();

    const __half* DdCol = g_Dd + (size_t)kb * ((size_t)DDROWS_ * N_) + 32 * w + lane;
    const unsigned FULL = 0xffffffffu;

    float one_r    = BIGV;   // R[i][.] at diag d-1
    float up_two_c = BIGV;   // cached shfl_up(two_r) == prev step's up_one

    const int NEPOCH = 2 * (NWARP_ - 1) + NWIN_;   // 74
    for (int e = 0; e < NEPOCH; e++) {
        int k = e - 2 * w;
        if (k >= 0 && k < NWIN_) {
            const int A = dstart + EW_ * k;

            float pre_a = BIGV, pre_b = BIGV;
            if (w > 0) {
                pre_a = bnd[w - 1][(A - 2 + lane) & RMASK_];
                pre_b = bnd[w - 1][(A + lane) & RMASK_];
            }

            if (k == 0) {
                float t0 = __shfl_sync(FULL, pre_a, 0);
                if (lane == 0) up_two_c = (w == 0) ? 0.f : t0;
            }

            #define STEP(s_, Dval_) {                                           \
                const int d = A + (s_);                                         \
                float b_one_v;                                                  \
                if ((s_) < 31) b_one_v = __shfl_sync(FULL, pre_a, (s_) + 1);    \
                else           b_one_v = __shfl_sync(FULL, pre_b, 30);          \
                if (w == 0) b_one_v = BIGV;                                     \
                float up_one = __shfl_up_sync(FULL, one_r, 1);                  \
                if (lane == 0) up_one = b_one_v;                                \
                int j = d - i;                                                  \
                float rv = BIGV;                                                \
                if (j >= 1 && j <= N_)                                          \
                    rv = (Dval_) + softmin3(up_two_c, up_one + WARPP,           \
                                            one_r + WARPP);                     \
                up_two_c = up_one;                                              \
                one_r = rv;                                                     \
                if (lane == 31) {                                               \
                    bnd[w][d & RMASK_] = rv;                                    \
                    if (w == NWARP_ - 1 && d == 2 * N_) g_d[kb] = rv;           \
                }                                                               \
            }

            float bufA[8], bufB[8], bufC[8];
            #pragma unroll
            for (int q = 0; q < 8; q++)
                bufA[q] = __half2float(__ldg(DdCol + (size_t)(A - 2 + q) * N_));
            #pragma unroll
            for (int q = 0; q < 8; q++)
                bufB[q] = __half2float(__ldg(DdCol + (size_t)(A + 6 + q) * N_));

            #pragma unroll
            for (int q = 0; q < 8; q++)
                bufC[q] = __half2float(__ldg(DdCol + (size_t)(A + 14 + q) * N_));
            #pragma unroll
            for (int q = 0; q < 8; q++) STEP(q, bufA[q]);

            #pragma unroll
            for (int q = 0; q < 8; q++)
                bufA[q] = __half2float(__ldg(DdCol + (size_t)(A + 22 + q) * N_));
            #pragma unroll
            for (int q = 0; q < 8; q++) STEP(8 + q, bufB[q]);

            #pragma unroll
            for (int q = 0; q < 8; q++) STEP(16 + q, bufC[q]);

            #pragma unroll
            for (int q = 0; q < 8; q++) STEP(24 + q, bufA[q]);

            #undef STEP
        }
        __syncthreads();
    }
}

// ============================================================
// Kernel 4: finalize scalar losses (parallel, ~6.5us).
// ============================================================
__global__ void finalize_kernel(const int* __restrict__ mel_lens,
                                const int* __restrict__ src_lens,
                                const float* __restrict__ durations,
                                const float* __restrict__ mus,
                                const float* __restrict__ log_vars,
                                const int* __restrict__ step_p,
                                float* __restrict__ out) {
    __shared__ float s_kl[8];
    __shared__ float s_dur[B_];
    __shared__ float s_d[KB_];

    int t    = threadIdx.x;      // 256 threads
    int lane = t & 31;
    int w    = t >> 5;

    {
        float lv = log_vars[t];
        float mu = mus[t];
        float kl = 1.f + lv - mu * mu - expf(lv);
        #pragma unroll
        for (int o = 16; o; o >>= 1) kl += __shfl_xor_sync(0xffffffffu, kl, o);
        if (lane == 0) s_kl[w] = kl;
    }

    {
        float ds = durations[w * S_ + lane] + durations[w * S_ + 32 + lane]
                 + durations[w * S_ + 64 + lane] + durations[w * S_ + 96 + lane];
        #pragma unroll
        for (int o = 16; o; o >>= 1) ds += __shfl_xor_sync(0xffffffffu, ds, o);
        if (lane == 0) s_dur[w] = ds;
    }

    if (t < KB_) s_d[t] = g_d[t];
    __syncthreads();

    if (t == 0) {
        float klsum = 0.f;
        #pragma unroll
        for (int i = 0; i < 8; i++) klsum += s_kl[i];
        float kl_loss = -0.5f * klsum;

        float sum_d = 0.f;
        #pragma unroll
        for (int p = 0; p < KB_; p++) sum_d += s_d[p];
        float mel_iter_loss = sum_d / (float)B_;

        float mel = 0.f, durl = 0.f;
        #pragma unroll
        for (int b = 0; b < B_; b++) {
            float len = (float)mel_lens[b];
            mel += mel_iter_loss / ((float)K_ * len);
            durl += fabsf(s_dur[b] - len) / (float)src_lens[b];
        }
        mel  /= (float)B_;
        durl  = 2.f * durl / (float)B_;

        int step = step_p[0];
        float beta;
        if (step < 2000)       beta = 0.f;
        else if (step >= 8000) beta = 1.f;
        else                   beta = (float)(step - 2000) / 6000.f;

        float total = mel + durl + beta * kl_loss;
        out[0] = total;
        out[1] = mel;
        out[2] = durl;
        out[3] = kl_loss;
        out[4] = beta;
    }
}

// ============================================================
extern "C" void kernel_launch(void* const* d_in, const int* in_sizes, int n_in,
                              void* d_out, int out_size) {
    const float* mel_iters   = (const float*)d_in[0];
    const float* mel_targets = (const float*)d_in[1];
    const int*   mel_lens    = (const int*)  d_in[2];
    const int*   src_lens    = (const int*)  d_in[3];
    const float* durations   = (const float*)d_in[4];
    const float* mus         = (const float*)d_in[5];
    const float* log_vars    = (const float*)d_in[6];
    const int*   step        = (const int*)  d_in[7];
    float*       out         = (float*)d_out;

    (void)in_sizes; (void)n_in; (void)out_size;

    const int total_rows = KB_ * N_ + B_ * N_;
    const int wpb = 8;
    prep_kernel<<<(total_rows + wpb - 1) / wpb, wpb * 32>>>(mel_iters, mel_targets);

    dim3 g((N_ + 63) / 64, (N_ + 63) / 64, KB_);
    dist_gemm_kernel<<<g, 256>>>();

    dtw_kernel<<<KB_, NWARP_ * 32>>>();

    finalize_kernel<<<1, 256>>>(mel_lens, src_lens, durations, mus, log_vars, step, out);
}

// round 16
// speedup vs baseline: 2.0770x; 1.3038x over previous
#include <cuda_runtime.h>
#include <math.h>

#define BIGV   100000000.0f
#define GAMMA_ 0.05f
#define INVG_  20.0f
#define WARPP  256.0f
#define K_     4
#define B_     8
#define KB_    32
#define N_     800
#define C_     80
#define S_     128
#define Z_     32

// diagonal-major D: g_Dd[kb][d-2][n] = D[n][m], d-2 = n+m (0-indexed)
#define DDROWS_ 1608

// ---- scratch (device globals; no runtime allocation) ----
__device__ float g_sx[(size_t)KB_ * N_ * C_];
__device__ float g_sy[(size_t)B_  * N_ * C_];
__device__ float g_x2[KB_ * N_];
__device__ float g_y2[B_  * N_];
__device__ float g_Dd[(size_t)KB_ * DDROWS_ * N_];
__device__ float g_d [KB_];

// ============================================================
// Kernel 1: sigmoid + squared row norms. One warp per row.
// ============================================================
__global__ void prep_kernel(const float* __restrict__ mel_iters,
                            const float* __restrict__ mel_targets) {
    int wid  = (blockIdx.x * blockDim.x + threadIdx.x) >> 5;
    int lane = threadIdx.x & 31;
    const int xrows = KB_ * N_;
    const int total = xrows + B_ * N_;
    if (wid >= total) return;

    const float* src;
    float* dst;
    float* nrm;
    if (wid < xrows) {
        src = mel_iters + (size_t)wid * C_;
        dst = g_sx      + (size_t)wid * C_;
        nrm = g_x2 + wid;
    } else {
        int r = wid - xrows;
        src = mel_targets + (size_t)r * C_;
        dst = g_sy        + (size_t)r * C_;
        nrm = g_y2 + r;
    }
    float acc = 0.f;
    for (int c = lane; c < C_; c += 32) {
        float v = src[c];
        float s = 1.f / (1.f + expf(-v));
        dst[c] = s;
        acc += s * s;
    }
    #pragma unroll
    for (int o = 16; o; o >>= 1) acc += __shfl_xor_sync(0xffffffffu, acc, o);
    if (lane == 0) *nrm = acc;
}

// ============================================================
// Kernel 2: distance GEMM with diagonal-major epilogue.
// (identical to the 612us version, fp32 D)
// ============================================================
__global__ void __launch_bounds__(256) dist_gemm_kernel() {
    __shared__ float sA[80 * 65];
    __shared__ float sB[80 * 65];

    const int kb = blockIdx.z;
    const int b  = kb & 7;
    const int m0 = blockIdx.x * 64;
    const int n0 = blockIdx.y * 64;
    const int t  = threadIdx.x;

    const float* xbase = g_sx + (size_t)kb * N_ * C_ + (size_t)n0 * C_;
    const float* ybase = g_sy + (size_t)b  * N_ * C_ + (size_t)m0 * C_;

    for (int e = t; e < 64 * 80; e += 256) {
        int r = e / 80;
        int c = e - r * 80;
        float xv = (n0 + r < N_) ? xbase[r * C_ + c] : 0.f;
        float yv = (m0 + r < N_) ? ybase[r * C_ + c] : 0.f;
        sA[c * 65 + r] = xv;
        sB[c * 65 + r] = yv;
    }
    __syncthreads();

    const int tx = t & 15;
    const int ty = t >> 4;

    float acc[4][4];
    #pragma unroll
    for (int i = 0; i < 4; i++)
        #pragma unroll
        for (int j = 0; j < 4; j++) acc[i][j] = 0.f;

    #pragma unroll 8
    for (int k = 0; k < 80; k++) {
        float a[4], bb[4];
        #pragma unroll
        for (int i = 0; i < 4; i++) a[i]  = sA[k * 65 + ty * 4 + i];
        #pragma unroll
        for (int j = 0; j < 4; j++) bb[j] = sB[k * 65 + tx * 4 + j];
        #pragma unroll
        for (int i = 0; i < 4; i++)
            #pragma unroll
            for (int j = 0; j < 4; j++)
                acc[i][j] = fmaf(a[i], bb[j], acc[i][j]);
    }

    // ---- epilogue: D values -> smem tile (stride 66) ----
    __syncthreads();
    float* sD = sA;

    {
        int nb = ty * 4, mb = tx * 4;
        float xn[4], ym[4];
        #pragma unroll
        for (int ii = 0; ii < 4; ii++) {
            int n = n0 + nb + ii;
            int m = m0 + mb + ii;
            xn[ii] = g_x2[kb * N_ + (n < N_ ? n : N_ - 1)];
            ym[ii] = g_y2[b  * N_ + (m < N_ ? m : N_ - 1)];
        }
        #pragma unroll
        for (int ii = 0; ii < 4; ii++)
            #pragma unroll
            for (int jj = 0; jj < 4; jj++)
                sD[(nb + ii) * 66 + (mb + jj)] = xn[ii] + ym[jj] - 2.f * acc[ii][jj];
    }
    __syncthreads();

    // ---- write 127 local anti-diagonals, coalesced in n ----
    {
        const int w8   = t >> 5;
        const int lane = t & 31;
        float* DdBase = g_Dd + (size_t)kb * ((size_t)DDROWS_ * N_);
        for (int ld = w8; ld < 127; ld += 8) {
            int nlo = ld > 63 ? ld - 63 : 0;
            int nhi = ld < 63 ? ld : 63;
            for (int nl = nlo + lane; nl <= nhi; nl += 32) {
                int ml = ld - nl;
                int n = n0 + nl, m = m0 + ml;
                if (n < N_ && m < N_)
                    DdBase[(size_t)(n + m) * N_ + n] = sD[nl * 66 + ml];
            }
        }
    }
}

// ============================================================
// Kernel 3: soft-DTW — epoch-skewed warp pipeline (R12 612us
// structure), with BRANCHLESS softmin: the fast-math logsumexp
// is computed unconditionally. For second>=1 cases the extra
// exp terms are < 2e-9, so 1+eps rounds to 1.0f and __logf
// returns exactly 0 -> sm == m bit-exactly (same as the old
// skipped path). No divergence, no predication on the chain.
// ============================================================
#define NWARP_  25
#define EW_     32
#define NWIN_   26
#define RINGSZ_ 128
#define RMASK_  (RINGSZ_ - 1)

__global__ void __launch_bounds__(NWARP_ * 32) dtw_kernel() {
    __shared__ float bnd[NWARP_][RINGSZ_];

    const int kb   = blockIdx.x;
    const int w    = threadIdx.x >> 5;
    const int lane = threadIdx.x & 31;
    const int i    = 32 * w + lane + 1;
    const int dstart = 32 * w + 2;

    __syncthreads();

    const float* DdCol = g_Dd + (size_t)kb * ((size_t)DDROWS_ * N_) + 32 * w + lane;
    const unsigned FULL = 0xffffffffu;

    float one_r    = BIGV;   // R[i][.] at diag d-1
    float up_two_c = BIGV;   // cached shfl_up(two_r) == prev step's up_one

    const int NEPOCH = 2 * (NWARP_ - 1) + NWIN_;   // 74
    for (int e = 0; e < NEPOCH; e++) {
        int k = e - 2 * w;
        if (k >= 0 && k < NWIN_) {
            const int A = dstart + EW_ * k;

            float pre_a = BIGV, pre_b = BIGV;
            if (w > 0) {
                pre_a = bnd[w - 1][(A - 2 + lane) & RMASK_];
                pre_b = bnd[w - 1][(A + lane) & RMASK_];
            }

            if (k == 0) {
                float t0 = __shfl_sync(FULL, pre_a, 0);
                if (lane == 0) up_two_c = (w == 0) ? 0.f : t0;
            }

            #define STEP(s_, Dval_) {                                           \
                const int d = A + (s_);                                         \
                float b_one_v;                                                  \
                if ((s_) < 31) b_one_v = __shfl_sync(FULL, pre_a, (s_) + 1);    \
                else           b_one_v = __shfl_sync(FULL, pre_b, 30);          \
                if (w == 0) b_one_v = BIGV;                                     \
                float up_one = __shfl_up_sync(FULL, one_r, 1);                  \
                if (lane == 0) up_one = b_one_v;                                \
                float av = up_two_c;                                            \
                float bu = up_one + WARPP;                                      \
                float cv = one_r + WARPP;                                       \
                float m  = fminf(av, fminf(bu, cv));                            \
                float es = __expf((m - av) * INVG_) +                           \
                           __expf((m - bu) * INVG_) +                           \
                           __expf((m - cv) * INVG_);                            \
                float sm = m - GAMMA_ * __logf(es);                             \
                int j = d - i;                                                  \
                float rv = (j >= 1 && j <= N_) ? ((Dval_) + sm) : BIGV;         \
                up_two_c = up_one;                                              \
                one_r = rv;                                                     \
                if (lane == 31) {                                               \
                    bnd[w][d & RMASK_] = rv;                                    \
                    if (w == NWARP_ - 1 && d == 2 * N_) g_d[kb] = rv;           \
                }                                                               \
            }

            float bufA[8], bufB[8], bufC[8];
            #pragma unroll
            for (int q = 0; q < 8; q++) bufA[q] = __ldg(DdCol + (size_t)(A - 2 + q) * N_);
            #pragma unroll
            for (int q = 0; q < 8; q++) bufB[q] = __ldg(DdCol + (size_t)(A + 6 + q) * N_);

            #pragma unroll
            for (int q = 0; q < 8; q++) bufC[q] = __ldg(DdCol + (size_t)(A + 14 + q) * N_);
            #pragma unroll
            for (int q = 0; q < 8; q++) STEP(q, bufA[q]);

            #pragma unroll
            for (int q = 0; q < 8; q++) bufA[q] = __ldg(DdCol + (size_t)(A + 22 + q) * N_);
            #pragma unroll
            for (int q = 0; q < 8; q++) STEP(8 + q, bufB[q]);

            #pragma unroll
            for (int q = 0; q < 8; q++) STEP(16 + q, bufC[q]);

            #pragma unroll
            for (int q = 0; q < 8; q++) STEP(24 + q, bufA[q]);

            #undef STEP
        }
        __syncthreads();
    }
}

// ============================================================
// Kernel 4: finalize scalar losses (parallel, ~6.5us).
// ============================================================
__global__ void finalize_kernel(const int* __restrict__ mel_lens,
                                const int* __restrict__ src_lens,
                                const float* __restrict__ durations,
                                const float* __restrict__ mus,
                                const float* __restrict__ log_vars,
                                const int* __restrict__ step_p,
                                float* __restrict__ out) {
    __shared__ float s_kl[8];
    __shared__ float s_dur[B_];
    __shared__ float s_d[KB_];

    int t    = threadIdx.x;      // 256 threads
    int lane = t & 31;
    int w    = t >> 5;

    {
        float lv = log_vars[t];
        float mu = mus[t];
        float kl = 1.f + lv - mu * mu - expf(lv);
        #pragma unroll
        for (int o = 16; o; o >>= 1) kl += __shfl_xor_sync(0xffffffffu, kl, o);
        if (lane == 0) s_kl[w] = kl;
    }

    {
        float ds = durations[w * S_ + lane] + durations[w * S_ + 32 + lane]
                 + durations[w * S_ + 64 + lane] + durations[w * S_ + 96 + lane];
        #pragma unroll
        for (int o = 16; o; o >>= 1) ds += __shfl_xor_sync(0xffffffffu, ds, o);
        if (lane == 0) s_dur[w] = ds;
    }

    if (t < KB_) s_d[t] = g_d[t];
    __syncthreads();

    if (t == 0) {
        float klsum = 0.f;
        #pragma unroll
        for (int i = 0; i < 8; i++) klsum += s_kl[i];
        float kl_loss = -0.5f * klsum;

        float sum_d = 0.f;
        #pragma unroll
        for (int p = 0; p < KB_; p++) sum_d += s_d[p];
        float mel_iter_loss = sum_d / (float)B_;

        float mel = 0.f, durl = 0.f;
        #pragma unroll
        for (int b = 0; b < B_; b++) {
            float len = (float)mel_lens[b];
            mel += mel_iter_loss / ((float)K_ * len);
            durl += fabsf(s_dur[b] - len) / (float)src_lens[b];
        }
        mel  /= (float)B_;
        durl  = 2.f * durl / (float)B_;

        int step = step_p[0];
        float beta;
        if (step < 2000)       beta = 0.f;
        else if (step >= 8000) beta = 1.f;
        else                   beta = (float)(step - 2000) / 6000.f;

        float total = mel + durl + beta * kl_loss;
        out[0] = total;
        out[1] = mel;
        out[2] = durl;
        out[3] = kl_loss;
        out[4] = beta;
    }
}

// ============================================================
extern "C" void kernel_launch(void* const* d_in, const int* in_sizes, int n_in,
                              void* d_out, int out_size) {
    const float* mel_iters   = (const float*)d_in[0];
    const float* mel_targets = (const float*)d_in[1];
    const int*   mel_lens    = (const int*)  d_in[2];
    const int*   src_lens    = (const int*)  d_in[3];
    const float* durations   = (const float*)d_in[4];
    const float* mus         = (const float*)d_in[5];
    const float* log_vars    = (const float*)d_in[6];
    const int*   step        = (const int*)  d_in[7];
    float*       out         = (float*)d_out;

    (void)in_sizes; (void)n_in; (void)out_size;

    const int total_rows = KB_ * N_ + B_ * N_;
    const int wpb = 8;
    prep_kernel<<<(total_rows + wpb - 1) / wpb, wpb * 32>>>(mel_iters, mel_targets);

    dim3 g((N_ + 63) / 64, (N_ + 63) / 64, KB_);
    dist_gemm_kernel<<<g, 256>>>();

    dtw_kernel<<<KB_, NWARP_ * 32>>>();

    finalize_kernel<<<1, 256>>>(mel_lens, src_lens, durations, mus, log_vars, step, out);
}

// round 17
// speedup vs baseline: 2.1754x; 1.0474x over previous
#include <cuda_runtime.h>
#include <math.h>

#define BIGV   100000000.0f
#define GAMMA_ 0.05f
#define INVG_  20.0f
#define WARPP  256.0f
#define K_     4
#define B_     8
#define KB_    32
#define N_     800
#define C_     80
#define S_     128
#define Z_     32

// diagonal-major D: g_Dd[kb][d-2][n] = D[n][m], d-2 = n+m (0-indexed)
// padded so RPT=2 prefetch (rows up to 1631) stays in bounds
#define DDROWS_ 1640

// ---- scratch (device globals; no runtime allocation) ----
__device__ float g_sx[(size_t)KB_ * N_ * C_];
__device__ float g_sy[(size_t)B_  * N_ * C_];
__device__ float g_x2[KB_ * N_];
__device__ float g_y2[B_  * N_];
__device__ float g_Dd[(size_t)KB_ * DDROWS_ * N_];
__device__ float g_d [KB_];

// ============================================================
// Kernel 1: sigmoid + squared row norms. One warp per row.
// ============================================================
__global__ void prep_kernel(const float* __restrict__ mel_iters,
                            const float* __restrict__ mel_targets) {
    int wid  = (blockIdx.x * blockDim.x + threadIdx.x) >> 5;
    int lane = threadIdx.x & 31;
    const int xrows = KB_ * N_;
    const int total = xrows + B_ * N_;
    if (wid >= total) return;

    const float* src;
    float* dst;
    float* nrm;
    if (wid < xrows) {
        src = mel_iters + (size_t)wid * C_;
        dst = g_sx      + (size_t)wid * C_;
        nrm = g_x2 + wid;
    } else {
        int r = wid - xrows;
        src = mel_targets + (size_t)r * C_;
        dst = g_sy        + (size_t)r * C_;
        nrm = g_y2 + r;
    }
    float acc = 0.f;
    for (int c = lane; c < C_; c += 32) {
        float v = src[c];
        float s = 1.f / (1.f + expf(-v));
        dst[c] = s;
        acc += s * s;
    }
    #pragma unroll
    for (int o = 16; o; o >>= 1) acc += __shfl_xor_sync(0xffffffffu, acc, o);
    if (lane == 0) *nrm = acc;
}

// ============================================================
// Kernel 2: distance GEMM with diagonal-major epilogue.
// (identical to the 501us version)
// ============================================================
__global__ void __launch_bounds__(256) dist_gemm_kernel() {
    __shared__ float sA[80 * 65];
    __shared__ float sB[80 * 65];

    const int kb = blockIdx.z;
    const int b  = kb & 7;
    const int m0 = blockIdx.x * 64;
    const int n0 = blockIdx.y * 64;
    const int t  = threadIdx.x;

    const float* xbase = g_sx + (size_t)kb * N_ * C_ + (size_t)n0 * C_;
    const float* ybase = g_sy + (size_t)b  * N_ * C_ + (size_t)m0 * C_;

    for (int e = t; e < 64 * 80; e += 256) {
        int r = e / 80;
        int c = e - r * 80;
        float xv = (n0 + r < N_) ? xbase[r * C_ + c] : 0.f;
        float yv = (m0 + r < N_) ? ybase[r * C_ + c] : 0.f;
        sA[c * 65 + r] = xv;
        sB[c * 65 + r] = yv;
    }
    __syncthreads();

    const int tx = t & 15;
    const int ty = t >> 4;

    float acc[4][4];
    #pragma unroll
    for (int i = 0; i < 4; i++)
        #pragma unroll
        for (int j = 0; j < 4; j++) acc[i][j] = 0.f;

    #pragma unroll 8
    for (int k = 0; k < 80; k++) {
        float a[4], bb[4];
        #pragma unroll
        for (int i = 0; i < 4; i++) a[i]  = sA[k * 65 + ty * 4 + i];
        #pragma unroll
        for (int j = 0; j < 4; j++) bb[j] = sB[k * 65 + tx * 4 + j];
        #pragma unroll
        for (int i = 0; i < 4; i++)
            #pragma unroll
            for (int j = 0; j < 4; j++)
                acc[i][j] = fmaf(a[i], bb[j], acc[i][j]);
    }

    // ---- epilogue: D values -> smem tile (stride 66) ----
    __syncthreads();
    float* sD = sA;

    {
        int nb = ty * 4, mb = tx * 4;
        float xn[4], ym[4];
        #pragma unroll
        for (int ii = 0; ii < 4; ii++) {
            int n = n0 + nb + ii;
            int m = m0 + mb + ii;
            xn[ii] = g_x2[kb * N_ + (n < N_ ? n : N_ - 1)];
            ym[ii] = g_y2[b  * N_ + (m < N_ ? m : N_ - 1)];
        }
        #pragma unroll
        for (int ii = 0; ii < 4; ii++)
            #pragma unroll
            for (int jj = 0; jj < 4; jj++)
                sD[(nb + ii) * 66 + (mb + jj)] = xn[ii] + ym[jj] - 2.f * acc[ii][jj];
    }
    __syncthreads();

    // ---- write 127 local anti-diagonals, coalesced in n ----
    {
        const int w8   = t >> 5;
        const int lane = t & 31;
        float* DdBase = g_Dd + (size_t)kb * ((size_t)DDROWS_ * N_);
        for (int ld = w8; ld < 127; ld += 8) {
            int nlo = ld > 63 ? ld - 63 : 0;
            int nhi = ld < 63 ? ld : 63;
            for (int nl = nlo + lane; nl <= nhi; nl += 32) {
                int ml = ld - nl;
                int n = n0 + nl, m = m0 + ml;
                if (n < N_ && m < N_)
                    DdBase[(size_t)(n + m) * N_ + n] = sD[nl * 66 + ml];
            }
        }
    }
}

// ============================================================
// Kernel 3: soft-DTW — epoch-skewed warp pipeline, RPT=2,
// fully BRANCHLESS softmin with the 2-exp sort trick:
//   the min arm's exp is exactly 1.0f, so
//   es = 1 + exp((m-mid)*20) + exp((m-max)*20); sm = m - g*log(es)
// (same value set as 3-exp version; exp(0)=1 exact).
// Structure/indexing identical to the R14 kernel (validated at
// rel_err 6.138612e-06); only the softmin body differs.
// One boundary shfl + one shfl_up serve BOTH cells per step.
// ============================================================
#define NW2_    13
#define LAG_    3
#define NWIN2_  27     // 27*32 = 864 >= N+63 = 863 diags per warp
#define RING2_  128
#define RM2_    (RING2_ - 1)

__global__ void __launch_bounds__(NW2_ * 32) dtw_kernel() {
    __shared__ float bnd[NW2_][RING2_];   // bnd[w][d & 127] = R[64w+64][d-(64w+64)]

    const int kb   = blockIdx.x;
    const int w    = threadIdx.x >> 5;
    const int lane = threadIdx.x & 31;
    const int i0   = 64 * w + 2 * lane + 1;
    const int i1   = i0 + 1;
    const bool v0  = (i0 <= N_);
    const bool v1  = (i1 <= N_);
    const int dstart = 64 * w + 2;

    __syncthreads();

    const float2* Dd2 = (const float2*)g_Dd
                      + (size_t)kb * ((size_t)DDROWS_ * (N_ / 2))
                      + 32 * w + lane;
    const unsigned FULL = 0xffffffffu;

    float one0 = BIGV;      // R[i0][d-1]
    float one1 = BIGV;      // R[i1][d-1]
    float two0 = BIGV;      // R[i0][d-2]
    float up_two_c = BIGV;  // R[i0-1][d-2] (cached from prev step's up_one)

    const int NEPOCH = LAG_ * (NW2_ - 1) + NWIN2_;   // 63
    for (int e = 0; e < NEPOCH; e++) {
        int k = e - LAG_ * w;
        if (k >= 0 && k < NWIN2_) {
            const int A = dstart + 32 * k;

            float pre_a = BIGV, pre_b = BIGV;
            if (w > 0) {
                pre_a = bnd[w - 1][(A - 2 + lane) & RM2_];
                pre_b = bnd[w - 1][(A + lane) & RM2_];
            }

            if (k == 0) {
                float t0 = __shfl_sync(FULL, pre_a, 0);
                if (lane == 0) up_two_c = (w == 0) ? 0.f : t0;  // R[0][0]=0 at d=2
            }

            #define STEP(s_, Dv_) {                                              \
                const int d = A + (s_);                                           \
                float b_one_v;                                                    \
                if ((s_) < 31) b_one_v = __shfl_sync(FULL, pre_a, (s_) + 1);      \
                else           b_one_v = __shfl_sync(FULL, pre_b, 30);            \
                if (w == 0) b_one_v = BIGV;                                       \
                float up_one = __shfl_up_sync(FULL, one1, 1);                     \
                if (lane == 0) up_one = b_one_v;                                  \
                float buW = up_one + WARPP;                                       \
                float c0W = one0 + WARPP;   /* left of cell0 == up of cell1 */    \
                float c1W = one1 + WARPP;                                         \
                int j0 = d - i0;                                                  \
                bool g0 = (j0 >= 1) && (j0 <= N_) && v0;                          \
                bool g1 = (j0 >= 2) && (j0 <= N_ + 1) && v1;  /* j1=j0-1 */       \
                /* cell0: arms (up_two_c, buW, c0W) */                            \
                float m0 = fminf(up_two_c, fminf(buW, c0W));                      \
                float x0 = fmaxf(up_two_c, fmaxf(buW, c0W));                      \
                float md0 = (up_two_c + buW + c0W) - m0 - x0;                     \
                float es0 = 1.0f + __expf((m0 - md0) * INVG_)                     \
                                 + __expf((m0 - x0) * INVG_);                     \
                float sm0 = m0 - GAMMA_ * __logf(es0);                            \
                /* cell1: arms (two0, c0W, c1W) */                                \
                float m1 = fminf(two0, fminf(c0W, c1W));                          \
                float x1 = fmaxf(two0, fmaxf(c0W, c1W));                          \
                float md1 = (two0 + c0W + c1W) - m1 - x1;                         \
                float es1 = 1.0f + __expf((m1 - md1) * INVG_)                     \
                                 + __expf((m1 - x1) * INVG_);                     \
                float sm1 = m1 - GAMMA_ * __logf(es1);                            \
                float rv0 = g0 ? ((Dv_).x + sm0) : BIGV;                          \
                float rv1 = g1 ? ((Dv_).y + sm1) : BIGV;                          \
                two0 = one0;                                                      \
                one0 = rv0;                                                       \
                one1 = rv1;                                                       \
                up_two_c = up_one;                                                \
                if (lane == 31) bnd[w][d & RM2_] = rv1;                           \
                if (d == 2 * N_ && i1 == N_) g_d[kb] = rv1;                       \
            }

            float2 bufA[8], bufB[8], bufC[8];
            #pragma unroll
            for (int q = 0; q < 8; q++) bufA[q] = Dd2[(size_t)(A - 2 + q) * (N_ / 2)];
            #pragma unroll
            for (int q = 0; q < 8; q++) bufB[q] = Dd2[(size_t)(A + 6 + q) * (N_ / 2)];

            #pragma unroll
            for (int q = 0; q < 8; q++) bufC[q] = Dd2[(size_t)(A + 14 + q) * (N_ / 2)];
            #pragma unroll
            for (int q = 0; q < 8; q++) STEP(q, bufA[q]);

            #pragma unroll
            for (int q = 0; q < 8; q++) bufA[q] = Dd2[(size_t)(A + 22 + q) * (N_ / 2)];
            #pragma unroll
            for (int q = 0; q < 8; q++) STEP(8 + q, bufB[q]);

            #pragma unroll
            for (int q = 0; q < 8; q++) STEP(16 + q, bufC[q]);

            #pragma unroll
            for (int q = 0; q < 8; q++) STEP(24 + q, bufA[q]);

            #undef STEP
        }
        __syncthreads();
    }
}

// ============================================================
// Kernel 4: finalize scalar losses (parallel, ~6.5us).
// ============================================================
__global__ void finalize_kernel(const int* __restrict__ mel_lens,
                                const int* __restrict__ src_lens,
                                const float* __restrict__ durations,
                                const float* __restrict__ mus,
                                const float* __restrict__ log_vars,
                                const int* __restrict__ step_p,
                                float* __restrict__ out) {
    __shared__ float s_kl[8];
    __shared__ float s_dur[B_];
    __shared__ float s_d[KB_];

    int t    = threadIdx.x;      // 256 threads
    int lane = t & 31;
    int w    = t >> 5;

    {
        float lv = log_vars[t];
        float mu = mus[t];
        float kl = 1.f + lv - mu * mu - expf(lv);
        #pragma unroll
        for (int o = 16; o; o >>= 1) kl += __shfl_xor_sync(0xffffffffu, kl, o);
        if (lane == 0) s_kl[w] = kl;
    }

    {
        float ds = durations[w * S_ + lane] + durations[w * S_ + 32 + lane]
                 + durations[w * S_ + 64 + lane] + durations[w * S_ + 96 + lane];
        #pragma unroll
        for (int o = 16; o; o >>= 1) ds += __shfl_xor_sync(0xffffffffu, ds, o);
        if (lane == 0) s_dur[w] = ds;
    }

    if (t < KB_) s_d[t] = g_d[t];
    __syncthreads();

    if (t == 0) {
        float klsum = 0.f;
        #pragma unroll
        for (int i = 0; i < 8; i++) klsum += s_kl[i];
        float kl_loss = -0.5f * klsum;

        float sum_d = 0.f;
        #pragma unroll
        for (int p = 0; p < KB_; p++) sum_d += s_d[p];
        float mel_iter_loss = sum_d / (float)B_;

        float mel = 0.f, durl = 0.f;
        #pragma unroll
        for (int b = 0; b < B_; b++) {
            float len = (float)mel_lens[b];
            mel += mel_iter_loss / ((float)K_ * len);
            durl += fabsf(s_dur[b] - len) / (float)src_lens[b];
        }
        mel  /= (float)B_;
        durl  = 2.f * durl / (float)B_;

        int step = step_p[0];
        float beta;
        if (step < 2000)       beta = 0.f;
        else if (step >= 8000) beta = 1.f;
        else                   beta = (float)(step - 2000) / 6000.f;

        float total = mel + durl + beta * kl_loss;
        out[0] = total;
        out[1] = mel;
        out[2] = durl;
        out[3] = kl_loss;
        out[4] = beta;
    }
}

// ============================================================
extern "C" void kernel_launch(void* const* d_in, const int* in_sizes, int n_in,
                              void* d_out, int out_size) {
    const float* mel_iters   = (const float*)d_in[0];
    const float* mel_targets = (const float*)d_in[1];
    const int*   mel_lens    = (const int*)  d_in[2];
    const int*   src_lens    = (const int*)  d_in[3];
    const float* durations   = (const float*)d_in[4];
    const float* mus         = (const float*)d_in[5];
    const float* log_vars    = (const float*)d_in[6];
    const int*   step        = (const int*)  d_in[7];
    float*       out         = (float*)d_out;

    (void)in_sizes; (void)n_in; (void)out_size;

    const int total_rows = KB_ * N_ + B_ * N_;
    const int wpb = 8;
    prep_kernel<<<(total_rows + wpb - 1) / wpb, wpb * 32>>>(mel_iters, mel_targets);

    dim3 g((N_ + 63) / 64, (N_ + 63) / 64, KB_);
    dist_gemm_kernel<<<g, 256>>>();

    dtw_kernel<<<KB_, NW2_ * 32>>>();

    finalize_kernel<<<1, 256>>>(mel_lens, src_lens, durations, mus, log_vars, step, out);
}